// round 5
// baseline (speedup 1.0000x reference)
#include <cuda_runtime.h>
#include <cstdint>

#define BATCH    16384
#define IN_DIM   512
#define NH       128
#define NO       256
#define NNODES   (NH + NO)         // 384
#define SRCW     (IN_DIM + NH)     // 640
#define TB       64                // batch rows per tile (float2 per lane)
#define NTHREADS 1024
#define NWARPS   32
#define MAXE     16384

// Persistent scratch rebuilt by prep each launch (deterministic).
__device__ int2 g_edges[MAXE];       // packed (q, w), sorted by (node, act)
__device__ int4 g_infoA[NNODES];     // per schedule slot: e0,e1,e2,e3
__device__ int2 g_infoB[NNODES];     // per schedule slot: e4, node_id

__device__ __forceinline__ float tanha(float z) {
    float r;
    asm("tanh.approx.f32 %0, %1;" : "=f"(r) : "f"(z));
    return r;
}

// ================= Fused prep: histogram + scan + scatter + LPT (1 block) =========
__global__ void __launch_bounds__(1024)
prep_all(const int* __restrict__ rows_h, const int* __restrict__ cols_h,
         const int* __restrict__ acts_h, const float* __restrict__ wh,
         const int* __restrict__ rows_o, const int* __restrict__ cols_o,
         const int* __restrict__ acts_o, const float* __restrict__ wo,
         int Eh, int Eo)
{
    __shared__ int cnt[NNODES * 4];
    __shared__ int off[NNODES * 4 + 1];
    __shared__ int wsum[32];

    const int tid = threadIdx.x, lane = tid & 31, wid = tid >> 5;

    for (int i = tid; i < NNODES * 4; i += 1024) cnt[i] = 0;
    __syncthreads();

    for (int e = tid; e < Eh; e += 1024)
        atomicAdd(&cnt[rows_h[e] * 4 + acts_h[e] - 1], 1);
    for (int e = tid; e < Eo; e += 1024)
        atomicAdd(&cnt[(NH + rows_o[e]) * 4 + acts_o[e] - 1], 1);
    __syncthreads();

    if (lane == 0) {
        const int base = wid * 48;
        int run = 0;
        for (int i = 0; i < 48; ++i) { off[base + i] = run; run += cnt[base + i]; }
        wsum[wid] = run;
    }
    __syncthreads();
    if (wid == 0) {
        const int v = wsum[lane];
        int ex = v;
        #pragma unroll
        for (int d = 1; d < 32; d <<= 1) {
            const int t = __shfl_up_sync(0xffffffffu, ex, d);
            if (lane >= d) ex += t;
        }
        ex -= v;
        wsum[lane] = ex;
        if (lane == 31) off[NNODES * 4] = ex + v;
    }
    __syncthreads();
    for (int i = tid; i < NNODES * 4; i += 1024) off[i] += wsum[i / 48];
    __syncthreads();

    for (int n = wid; n < NNODES; n += 32) {
        const bool hid = n < NH;
        const int* cols = hid ? cols_h : cols_o;
        const int* acts = hid ? acts_h : acts_o;
        const float* wp = hid ? wh : wo;
        const int sub = hid ? 0 : Eh;
        const int s = off[n * 4] - sub;
        const int e = off[(n + 1) * 4] - sub;
        int d0 = off[n * 4], d1 = off[n * 4 + 1], d2 = off[n * 4 + 2], d3 = off[n * 4 + 3];
        for (int c = s; c < e; c += 32) {
            const int idx = c + lane;
            const bool v = idx < e;
            const int act = v ? acts[idx] : 0;
            const int col = v ? cols[idx] : 0;
            const float w = v ? wp[idx] : 0.f;
            const int pk = col * 256 | ((col & 31) << 3);
            #pragma unroll
            for (int a = 1; a <= 4; ++a) {
                const unsigned mm = __ballot_sync(0xffffffffu, act == a);
                int& d = (a == 1) ? d0 : (a == 2) ? d1 : (a == 3) ? d2 : d3;
                if (act == a) {
                    const int r = __popc(mm & ((1u << lane) - 1));
                    const float ww = (a == 4) ? 0.5f * w : w;   // sigmoid pre-halved
                    g_edges[d + r] = make_int2(pk, __float_as_int(ww));
                }
                d += __popc(mm);
            }
        }
    }
    __syncthreads();

    if (tid < NNODES) {
        const int n = tid;
        const bool hid = n < NH;
        const int cn = off[(n + 1) * 4] - off[n * 4];
        const int lo = hid ? 0 : NH, hi2 = hid ? NH : NNODES;
        int rank = 0;
        for (int j = lo; j < hi2; ++j) {
            const int cj = off[(j + 1) * 4] - off[j * 4];
            rank += (cj > cn) || (cj == cn && j < n);
        }
        const int r = rank >> 5;
        int wl = rank & 31;
        if (r & 1) wl = 31 - wl;
        const int slot = (hid ? 0 : NH) + r * 32 + wl;
        g_infoA[slot] = make_int4(off[n * 4], off[n * 4 + 1], off[n * 4 + 2], off[n * 4 + 3]);
        g_infoB[slot] = make_int2(off[(n + 1) * 4], hid ? n : n - NH);
    }
}

// ================= Main kernel ====================================================
// Paired-edge segment loop: one LDS.128 per 2 edges (even-aligned), scalar head/tail.
#define SEG_LOOP(E0, E1, BODY1, BODY2) do {                                  \
    int e = (E0);                                                            \
    const int e_end = (E1);                                                  \
    if ((e < e_end) && (e & 1)) {                                            \
        const int2 ed = se[e];                                               \
        const float2 s = *(const float2*)(srcb + (ed.x ^ lane8));            \
        const float w = __int_as_float(ed.y);                                \
        BODY1                                                                \
        ++e;                                                                 \
    }                                                                        \
    _Pragma("unroll 2")                                                      \
    for (; e + 1 < e_end; e += 2) {                                          \
        const int4 ep = *(const int4*)(se + e);                              \
        const float2 sA = *(const float2*)(srcb + (ep.x ^ lane8));           \
        const float2 sB = *(const float2*)(srcb + (ep.z ^ lane8));           \
        const float wA = __int_as_float(ep.y);                               \
        const float wB = __int_as_float(ep.w);                               \
        BODY2                                                                \
    }                                                                        \
    if (e < e_end) {                                                         \
        const int2 ed = se[e];                                               \
        const float2 s = *(const float2*)(srcb + (ed.x ^ lane8));            \
        const float w = __int_as_float(ed.y);                                \
        BODY1                                                                \
    }                                                                        \
} while (0)

__device__ __forceinline__ float2 node_accum(const int2* __restrict__ se,
                                             const char* __restrict__ srcb,
                                             int lane8, int4 A, int e4)
{
    float a0 = 0.f, a1 = 0.f, b0 = 0.f, b1 = 0.f;
    // identity
    SEG_LOOP(A.x, A.y,
        { a0 = fmaf(w, s.x, a0); a1 = fmaf(w, s.y, a1); },
        { a0 = fmaf(wA, sA.x, a0); a1 = fmaf(wA, sA.y, a1);
          b0 = fmaf(wB, sB.x, b0); b1 = fmaf(wB, sB.y, b1); });
    // tanh
    SEG_LOOP(A.y, A.z,
        { a0 += tanha(w * s.x); a1 += tanha(w * s.y); },
        { a0 += tanha(wA * sA.x); a1 += tanha(wA * sA.y);
          b0 += tanha(wB * sB.x); b1 += tanha(wB * sB.y); });
    // relu
    SEG_LOOP(A.z, A.w,
        { a0 += fmaxf(w * s.x, 0.f); a1 += fmaxf(w * s.y, 0.f); },
        { a0 += fmaxf(wA * sA.x, 0.f); a1 += fmaxf(wA * sA.y, 0.f);
          b0 += fmaxf(wB * sB.x, 0.f); b1 += fmaxf(wB * sB.y, 0.f); });
    // sigmoid (w pre-halved; +0.5 per edge folded into bias)
    SEG_LOOP(A.w, e4,
        { a0 = fmaf(0.5f, tanha(w * s.x), a0); a1 = fmaf(0.5f, tanha(w * s.y), a1); },
        { a0 = fmaf(0.5f, tanha(wA * sA.x), a0); a1 = fmaf(0.5f, tanha(wA * sA.y), a1);
          b0 = fmaf(0.5f, tanha(wB * sB.x), b0); b1 = fmaf(0.5f, tanha(wB * sB.y), b1); });
    const float bias = 0.5f * (float)(e4 - A.w);
    return make_float2(a0 + b0 + bias, a1 + b1 + bias);
}

__global__ void __launch_bounds__(NTHREADS, 1)
wann_main(const float* __restrict__ x, float* __restrict__ out, int Etot)
{
    extern __shared__ char sm[];
    float*  src = (float*)sm;                        // [640*64] swizzled transposed
    int2*   se  = (int2*)(sm + SRCW * TB * 4);       // [Etot] packed edges
    float2* buf = (float2*)sm;                       // ALIASES src: [NO][33] after compute

    const int tid = threadIdx.x, wid = tid >> 5, lane = tid & 31;
    const int lane8 = lane << 3;
    const char* srcb = (const char*)sm;
    const int b0t = blockIdx.x * TB;

    // ---- stage edges into SMEM ----
    for (int i = tid; i < Etot; i += NTHREADS) se[i] = g_edges[i];

    // ---- stage x tile into swizzled transposed SMEM ----
    {
        const int sub = lane & 7, bq = lane >> 3;
        for (int it = wid; it < 256; it += NWARPS) {
            const int cchunk = it & 15;
            const int bchunk = it >> 4;
            const int b = bchunk * 4 + bq;
            const int c = cchunk * 32 + sub * 4;
            const float4 v = *(const float4*)(x + (size_t)(b0t + b) * IN_DIM + c);
            #pragma unroll
            for (int j = 0; j < 4; ++j) {
                const int cc = c + j;
                const int g = cc * 32 + ((b >> 1) ^ (cc & 31));
                const float val = (j == 0) ? v.x : (j == 1) ? v.y : (j == 2) ? v.z : v.w;
                src[2 * g + (b & 1)] = val;
            }
        }
    }
    __syncthreads();

    // ---- hidden phase: warp = node (LPT), unroll-1 with info prefetch ----
    {
        int4 A  = __ldg(&g_infoA[wid]);
        int2 Bi = __ldg(&g_infoB[wid]);
        #pragma unroll 1
        for (int rr = 0; rr < NH / NWARPS; ++rr) {
            int4 An; int2 Bn;
            if (rr + 1 < NH / NWARPS) {
                An = __ldg(&g_infoA[(rr + 1) * NWARPS + wid]);
                Bn = __ldg(&g_infoB[(rr + 1) * NWARPS + wid]);
            }
            const float2 r = node_accum(se, srcb, lane8, A, Bi.x);
            const int hc = IN_DIM + Bi.y;
            const int qh = hc * 256 | ((hc & 31) << 3);
            *(float2*)((char*)sm + (qh ^ lane8)) = r;
            A = An; Bi = Bn;
        }
    }
    __syncthreads();

    // ---- output phase: 8 nodes per warp, fully unrolled (res in regs) ----
    float2 res[NO / NWARPS];
    int    onode[NO / NWARPS];
    #pragma unroll
    for (int rr = 0; rr < NO / NWARPS; ++rr) {
        const int slot = NH + rr * NWARPS + wid;
        const int4 A  = __ldg(&g_infoA[slot]);
        const int2 Bi = __ldg(&g_infoB[slot]);
        onode[rr] = Bi.y;
        const float2 r = node_accum(se, srcb, lane8, A, Bi.x);
        res[rr] = make_float2(tanha(r.x), tanha(r.y));
    }

    // ---- write-out: one scatter into full transpose buffer, then coalesced ----
    __syncthreads();                 // all src reads done; buf may alias src
    #pragma unroll
    for (int rr = 0; rr < NO / NWARPS; ++rr)
        buf[onode[rr] * 33 + lane] = res[rr];
    __syncthreads();
    #pragma unroll
    for (int ch = 0; ch < NO / 32; ++ch) {
        #pragma unroll
        for (int r2 = 0; r2 < 2; ++r2) {
            const int rb = wid + r2 * 32;
            const float2 v = buf[(ch * 32 + lane) * 33 + (rb >> 1)];
            out[(size_t)(b0t + rb) * NO + ch * 32 + lane] = (rb & 1) ? v.y : v.x;
        }
    }
}

extern "C" void kernel_launch(void* const* d_in, const int* in_sizes, int n_in,
                              void* d_out, int out_size)
{
    const float* x      = (const float*)d_in[0];
    const float* wh     = (const float*)d_in[1];
    const float* wo     = (const float*)d_in[2];
    const int*   rows_h = (const int*)d_in[3];
    const int*   cols_h = (const int*)d_in[4];
    const int*   acts_h = (const int*)d_in[5];
    const int*   rows_o = (const int*)d_in[6];
    const int*   cols_o = (const int*)d_in[7];
    const int*   acts_o = (const int*)d_in[8];
    float* out = (float*)d_out;

    const int Eh = in_sizes[1];
    const int Eo = in_sizes[2];
    const int Etot = Eh + Eo;

    prep_all<<<1, 1024>>>(rows_h, cols_h, acts_h, wh,
                          rows_o, cols_o, acts_o, wo, Eh, Eo);

    const size_t smem = (size_t)SRCW * TB * 4 + (size_t)Etot * 8;
    cudaFuncSetAttribute(wann_main, cudaFuncAttributeMaxDynamicSharedMemorySize,
                         (int)smem);
    wann_main<<<BATCH / TB, NTHREADS, smem>>>(x, out, Etot);
}